// round 16
// baseline (speedup 1.0000x reference)
#include <cuda_runtime.h>
#include <cuda_fp16.h>
#include <cstdint>

#define N_NODES 50000
#define N_EDGES 600000
#define N_RELS  500
#define DIM     128
#define M_PAD   50048
#define NTILES  391
#define GRID_F  296          // exactly 2 CTAs/SM * 148 SMs -> single wave
#define EPC     2028         // ceil(600000/296) edges per CTA

typedef unsigned int u32;
typedef unsigned short u16;

// ---------------------------------------------------------------------------
// Device scratch (all fp16) + grid barrier
// ---------------------------------------------------------------------------
__device__ __align__(16) u16 g_S16[(size_t)M_PAD * DIM];
__device__ __align__(16) u16 g_h16[(size_t)M_PAD * DIM];
__device__ __align__(16) u16 g_rel16[N_RELS * DIM];
__device__ __align__(16) u16 g_B[256 * DIM];    // [Wn(0..127); Wl(128..255)] fp16 [K][N]
__device__ u32 g_bar;

__device__ __forceinline__ u32 pack_h2(float lo, float hi) {
    u32 r;
    asm("cvt.rn.f16x2.f32 %0, %1, %2;" : "=r"(r) : "f"(hi), "f"(lo));
    return r;
}

// ---------------------------------------------------------------------------
// Kernel 1: unified init (grid-stride) + barrier reset
// ---------------------------------------------------------------------------
#define IT0 (N_NODES * DIM / 8)
#define IT1 (IT0 + M_PAD * DIM / 8)
#define IT2 (IT1 + N_RELS * DIM / 8)
#define IT3 (IT2 + 256 * DIM / 8)

__global__ void __launch_bounds__(256) init_kernel(
    const float* __restrict__ h,
    const float* __restrict__ rel_emb,
    const float* __restrict__ W_neighbor,
    const float* __restrict__ loop_weight)
{
    if (blockIdx.x == 0 && threadIdx.x == 0) g_bar = 0;
    for (int i = blockIdx.x * 256 + threadIdx.x; i < IT3; i += gridDim.x * 256) {
        if (i < IT0) {
            ((uint4*)g_S16)[i] = make_uint4(0, 0, 0, 0);
        } else if (i < IT1) {
            int j   = i - IT0;
            int row = j >> 4;
            int sg  = j & 15;
            uint4 o = make_uint4(0, 0, 0, 0);
            if (row < N_NODES) {
                const float4* src = (const float4*)(h + (size_t)row * DIM + sg * 8);
                float4 a = src[0], b = src[1];
                o.x = pack_h2(a.x, a.y); o.y = pack_h2(a.z, a.w);
                o.z = pack_h2(b.x, b.y); o.w = pack_h2(b.z, b.w);
            }
            ((uint4*)g_h16)[j] = o;
        } else if (i < IT2) {
            int j = i - IT1;
            const float4* src = (const float4*)(rel_emb + (size_t)j * 8);
            float4 a = src[0], b = src[1];
            uint4 o;
            o.x = pack_h2(a.x, a.y); o.y = pack_h2(a.z, a.w);
            o.z = pack_h2(b.x, b.y); o.w = pack_h2(b.z, b.w);
            ((uint4*)g_rel16)[j] = o;
        } else {
            int j = i - IT2;                 // < 4096
            int k = j >> 4;
            int sg = j & 15;
            const float* src = (k < 128) ? (W_neighbor + (size_t)k * DIM + sg * 8)
                                         : (loop_weight + (size_t)(k - 128) * DIM + sg * 8);
            float4 a = ((const float4*)src)[0], b = ((const float4*)src)[1];
            uint4 o;
            o.x = pack_h2(a.x, a.y); o.y = pack_h2(a.z, a.w);
            o.z = pack_h2(b.x, b.y); o.w = pack_h2(b.z, b.w);
            ((uint4*)g_B)[j] = o;
        }
    }
}

// ---------------------------------------------------------------------------
// GEMM helpers
// ---------------------------------------------------------------------------
#define A_STRIDE 144
#define B_STRIDE 272
#define OFF_A(s) ((s) * 18432)
#define OFF_B(s) (36864 + (s) * 17408)
#define SM_TOTAL 71680

__device__ __forceinline__ void ldsm4(u32* r, u32 addr) {
    asm volatile("ldmatrix.sync.aligned.m8n8.x4.shared.b16 {%0,%1,%2,%3}, [%4];"
                 : "=r"(r[0]), "=r"(r[1]), "=r"(r[2]), "=r"(r[3]) : "r"(addr));
}
__device__ __forceinline__ void ldsm4t(u32* r, u32 addr) {
    asm volatile("ldmatrix.sync.aligned.m8n8.x4.trans.shared.b16 {%0,%1,%2,%3}, [%4];"
                 : "=r"(r[0]), "=r"(r[1]), "=r"(r[2]), "=r"(r[3]) : "r"(addr));
}
__device__ __forceinline__ void mma16816(float* d, const u32* a, u32 b0, u32 b1) {
    asm volatile("mma.sync.aligned.m16n8k16.row.col.f32.f16.f16.f32 "
                 "{%0,%1,%2,%3}, {%4,%5,%6,%7}, {%8,%9}, {%0,%1,%2,%3};"
                 : "+f"(d[0]), "+f"(d[1]), "+f"(d[2]), "+f"(d[3])
                 : "r"(a[0]), "r"(a[1]), "r"(a[2]), "r"(a[3]), "r"(b0), "r"(b1));
}
__device__ __forceinline__ void cp16(u32 dst, const void* src) {
    asm volatile("cp.async.cg.shared.global [%0], [%1], 16;" :: "r"(dst), "l"(src) : "memory");
}
#define CP_COMMIT() asm volatile("cp.async.commit_group;" ::: "memory")

// cp.async A from g_h16 (koff halves) into stage s
__device__ __forceinline__ void issue_A_h(u32 sbase, int tid, int row0, int koff, int s)
{
    u32 ab = sbase + OFF_A(s);
#pragma unroll
    for (int it = 0; it < 4; it++) {
        int i  = tid + it * 256;
        int r  = i >> 3;
        int sg = i & 7;
        cp16(ab + (u32)(r * A_STRIDE + sg * 16),
             (const char*)(g_h16 + (size_t)(row0 + r) * DIM + koff) + sg * 16);
    }
}
// cp.async B rows [krow0, krow0+64) into stage s
__device__ __forceinline__ void issue_B(u32 sbase, int tid, int krow0, int s)
{
    u32 bb = sbase + OFF_B(s);
#pragma unroll
    for (int it = 0; it < 4; it++) {
        int i  = tid + it * 256;
        int r  = i >> 4;
        int sg = i & 15;
        cp16(bb + (u32)(r * B_STRIDE + sg * 16),
             (const char*)g_B + (size_t)(krow0 + r) * 256 + sg * 16);
    }
}

// stage A chunk c (S half): LDG fp16 S, fp32 norm scale, repack, STS
__device__ __forceinline__ void stage_A_S(const float* __restrict__ norm,
                                          int row0, int c, int tid,
                                          char* smem, u32 a_off)
{
    int row  = tid >> 1;
    int half = tid & 1;
    int gr   = row0 + row;
    float sc = (gr < N_NODES) ? __ldg(norm + gr) : 0.f;
    const uint4* src = (const uint4*)(g_S16 + (size_t)gr * DIM + c * 64 + half * 32);
    u32 ob = a_off + (u32)(row * A_STRIDE + half * 64);
#pragma unroll
    for (int p = 0; p < 4; p++) {
        uint4 v = src[p];
        const u32* vv = (const u32*)&v;
        uint4 o;
        u32* oo = (u32*)&o;
#pragma unroll
        for (int q = 0; q < 4; q++) {
            float2 f = __half22float2(*(const __half2*)&vv[q]);
            oo[q] = pack_h2(f.x * sc, f.y * sc);
        }
        *(uint4*)(smem + ob + p * 16) = o;
    }
}

// compute one 64-K chunk (all 8 warps, 32x64 warp tiles)
__device__ __forceinline__ void compute_chunk(
    u32 a_sm, u32 b_sm, int lane, int warp_m, int warp_n, float acc[2][8][4])
{
#pragma unroll
    for (int k16 = 0; k16 < 4; k16++) {
        u32 bh[4][4];
#pragma unroll
        for (int ng = 0; ng < 4; ng++) {
            u32 baddr = b_sm
                      + (u32)((k16 * 16 + (lane & 15)) * B_STRIDE)
                      + (u32)((warp_n * 64 + ng * 16 + (lane >> 4) * 8) * 2);
            ldsm4t(bh[ng], baddr);
        }
#pragma unroll
        for (int mi = 0; mi < 2; mi++) {
            u32 aaddr = a_sm
                      + (u32)((warp_m * 32 + mi * 16 + (lane & 15)) * A_STRIDE)
                      + (u32)(k16 * 32 + (lane >> 4) * 16);
            u32 ah[4];
            ldsm4(ah, aaddr);
#pragma unroll
            for (int ni = 0; ni < 8; ni++) {
                int ng = ni >> 1;
                int hf = (ni & 1) * 2;
                mma16816(acc[mi][ni], ah, bh[ng][hf], bh[ng][hf + 1]);
            }
        }
    }
}

// one edge: S16[dst] += h16[src] + rel16[type]
__device__ __forceinline__ void do_edge(
    const int* __restrict__ edge_src, const int* __restrict__ edge_dst,
    const int* __restrict__ edge_type, int e, int l16)
{
    int s = __ldg(edge_src  + e);
    int d = __ldg(edge_dst  + e);
    int t = __ldg(edge_type + e);
    const uint4 hv = *(const uint4*)(g_h16   + (size_t)s * DIM + l16 * 8);
    const uint4 rv = *(const uint4*)(g_rel16 + (size_t)t * DIM + l16 * 8);
    u32 m0, m1, m2, m3;
    asm("add.rn.f16x2 %0, %1, %2;" : "=r"(m0) : "r"(hv.x), "r"(rv.x));
    asm("add.rn.f16x2 %0, %1, %2;" : "=r"(m1) : "r"(hv.y), "r"(rv.y));
    asm("add.rn.f16x2 %0, %1, %2;" : "=r"(m2) : "r"(hv.z), "r"(rv.z));
    asm("add.rn.f16x2 %0, %1, %2;" : "=r"(m3) : "r"(hv.w), "r"(rv.w));
    u16* outp = g_S16 + (size_t)d * DIM + l16 * 8;
    asm volatile("red.global.add.noftz.v4.f16x2 [%0], {%1, %2, %3, %4};"
                 :: "l"(outp), "r"(m0), "r"(m1), "r"(m2), "r"(m3) : "memory");
}

// ---------------------------------------------------------------------------
// Kernel 2: fused scatter + GEMM.  Single wave (296 CTAs, 2/SM).
//   phase 1: scatter my EPC edges; fence; arrive on g_bar
//   phase 2: compute h@Wl half (prefetched at kernel start) — hides stragglers
//   phase 3: prefetch Wn B; spin until g_bar==296; stage norm*S; compute; store
// ---------------------------------------------------------------------------
__global__ void __launch_bounds__(256, 2) fused_kernel(
    const int*   __restrict__ edge_src,
    const int*   __restrict__ edge_dst,
    const int*   __restrict__ edge_type,
    const float* __restrict__ norm,
    float*       __restrict__ out)
{
    extern __shared__ char smem[];
    u32 sbase;
    asm("{ .reg .u64 t; cvta.to.shared.u64 t, %1; cvt.u32.u64 %0, t; }"
        : "=r"(sbase) : "l"(smem));

    const int tid    = threadIdx.x;
    const int wid    = tid >> 5;
    const int lane   = tid & 31;
    const int warp_m = wid & 3;
    const int warp_n = wid >> 2;
    const int row0   = blockIdx.x * 128;   // blockIdx.x < 296; rows 0..37887? no:
    // NTILES=391 > 296: CTA b owns tile b only if b < NTILES... but 296 < 391!
    // -> each CTA must handle ceil(391/296)=2 tiles?  NO: keep 1 tile per CTA is
    // impossible.  Instead: CTA b handles tiles b and b+296 (second only if valid).

    // prologue: prefetch h chunks for FIRST tile (G0: h-k0, G1: h-k64)
    issue_A_h(sbase, tid, row0, 0, 0);
    issue_B(sbase, tid, 128, 0);
    CP_COMMIT();                                   // G0
    issue_A_h(sbase, tid, row0, 64, 1);
    issue_B(sbase, tid, 192, 1);
    CP_COMMIT();                                   // G1

    // ---------------- phase 1: scatter ----------------
    {
        int e0 = blockIdx.x * EPC;
        int e1 = e0 + EPC; if (e1 > N_EDGES) e1 = N_EDGES;
        int l16 = lane & 15;
        int e = e0 + wid * 2 + (lane >> 4);
        for (; e + 16 < e1; e += 32) {
            do_edge(edge_src, edge_dst, edge_type, e, l16);
            do_edge(edge_src, edge_dst, edge_type, e + 16, l16);
        }
        for (; e < e1; e += 16)
            do_edge(edge_src, edge_dst, edge_type, e, l16);
    }
    __threadfence();
    __syncthreads();
    if (tid == 0) atomicAdd(&g_bar, 1);

    // process tiles b and b+296
    for (int pass = 0; pass < 2; pass++) {
        const int tile = blockIdx.x + pass * GRID_F;
        if (tile >= NTILES) break;
        const int trow0 = tile * 128;

        if (pass == 1) {
            // prefetch h chunks for second tile (stages free after pass 0)
            issue_A_h(sbase, tid, trow0, 0, 0);
            issue_B(sbase, tid, 128, 0);
            CP_COMMIT();
            issue_A_h(sbase, tid, trow0, 64, 1);
            issue_B(sbase, tid, 192, 1);
            CP_COMMIT();
        }

        float acc[2][8][4];
#pragma unroll
        for (int mi = 0; mi < 2; mi++)
#pragma unroll
            for (int ni = 0; ni < 8; ni++)
#pragma unroll
                for (int q = 0; q < 4; q++) acc[mi][ni][q] = 0.f;

        // -------- phase 2: h @ Wl half --------
        asm volatile("cp.async.wait_group 1;" ::: "memory");
        __syncthreads();
        compute_chunk(sbase + OFF_A(0), sbase + OFF_B(0), lane, warp_m, warp_n, acc);
        __syncthreads();
        issue_B(sbase, tid, 0, 0);          // Wn rows 0-63 -> stage0 B
        CP_COMMIT();                                   // G2
        asm volatile("cp.async.wait_group 1;" ::: "memory");
        __syncthreads();
        compute_chunk(sbase + OFF_A(1), sbase + OFF_B(1), lane, warp_m, warp_n, acc);
        __syncthreads();
        issue_B(sbase, tid, 64, 1);         // Wn rows 64-127 -> stage1 B
        CP_COMMIT();                                   // G3

        // -------- phase 3: wait for global scatter completion --------
        if (pass == 0) {
            if (tid == 0) {
                u32 v;
                for (;;) {
                    asm volatile("ld.acquire.gpu.global.u32 %0, [%1];"
                                 : "=r"(v) : "l"(&g_bar));
                    if (v == GRID_F) break;
                    asm volatile("nanosleep.u32 128;");
                }
            }
            __syncthreads();
        }

        // stage + compute S chunks (norm applied in fp32 during staging)
        stage_A_S(norm, trow0, 0, tid, smem, OFF_A(0));
        asm volatile("cp.async.wait_group 1;" ::: "memory");
        __syncthreads();
        compute_chunk(sbase + OFF_A(0), sbase + OFF_B(0), lane, warp_m, warp_n, acc);
        __syncthreads();
        stage_A_S(norm, trow0, 1, tid, smem, OFF_A(1));
        asm volatile("cp.async.wait_group 0;" ::: "memory");
        __syncthreads();
        compute_chunk(sbase + OFF_A(1), sbase + OFF_B(1), lane, warp_m, warp_n, acc);
        __syncthreads();   // all warps done with smem before next pass refills

        // -------- epilogue: relu + store --------
#pragma unroll
        for (int mi = 0; mi < 2; mi++) {
            int r0 = trow0 + warp_m * 32 + mi * 16 + (lane >> 2);
#pragma unroll
            for (int ni = 0; ni < 8; ni++) {
                int col = warp_n * 64 + ni * 8 + (lane & 3) * 2;
                if (r0 < N_NODES) {
                    float2 v;
                    v.x = fmaxf(acc[mi][ni][0], 0.f);
                    v.y = fmaxf(acc[mi][ni][1], 0.f);
                    *(float2*)(out + (size_t)r0 * DIM + col) = v;
                }
                if (r0 + 8 < N_NODES) {
                    float2 v;
                    v.x = fmaxf(acc[mi][ni][2], 0.f);
                    v.y = fmaxf(acc[mi][ni][3], 0.f);
                    *(float2*)(out + (size_t)(r0 + 8) * DIM + col) = v;
                }
            }
        }
    }
}

// ---------------------------------------------------------------------------
// Launcher
// ---------------------------------------------------------------------------
extern "C" void kernel_launch(void* const* d_in, const int* in_sizes, int n_in,
                              void* d_out, int out_size)
{
    (void)in_sizes; (void)n_in; (void)out_size;

    const float* h          = (const float*)d_in[0];
    const float* norm       = (const float*)d_in[1];
    const float* rel_emb    = (const float*)d_in[2];
    const float* W_neighbor = (const float*)d_in[3];
    const float* loop_w     = (const float*)d_in[4];
    const int*   edge_src   = (const int*)d_in[5];
    const int*   edge_dst   = (const int*)d_in[6];
    const int*   edge_type  = (const int*)d_in[7];
    float*       out        = (float*)d_out;

    init_kernel<<<1184, 256>>>(h, rel_emb, W_neighbor, loop_w);
    {
        static bool attr_set = false;
        if (!attr_set) {
            cudaFuncSetAttribute(fused_kernel,
                                 cudaFuncAttributeMaxDynamicSharedMemorySize, SM_TOTAL);
            attr_set = true;
        }
        fused_kernel<<<GRID_F, 256, SM_TOTAL>>>(edge_src, edge_dst, edge_type, norm, out);
    }
}

// round 17
// speedup vs baseline: 1.3103x; 1.3103x over previous
#include <cuda_runtime.h>
#include <cuda_fp16.h>
#include <cstdint>

#define N_NODES 50000
#define N_EDGES 600000
#define N_RELS  500
#define DIM     128
#define M_PAD   50048
#define NTILES  391          // ceil(50000/128)

typedef unsigned int u32;
typedef unsigned short u16;

// ---------------------------------------------------------------------------
// Device scratch (all fp16)
// ---------------------------------------------------------------------------
__device__ __align__(16) u16 g_S16[(size_t)M_PAD * DIM];      // fp16 scatter accumulator
__device__ __align__(16) u16 g_h16[(size_t)M_PAD * DIM];      // fp16 h (padded w/ zeros)
__device__ __align__(16) u16 g_rel16[N_RELS * DIM];           // fp16 rel_emb
__device__ __align__(16) u16 g_B[256 * DIM];                  // B=[Wn;Wl] fp16 [K=256][N=128]

__device__ __forceinline__ u32 pack_h2(float lo, float hi) {
    u32 r;
    asm("cvt.rn.f16x2.f32 %0, %1, %2;" : "=r"(r) : "f"(hi), "f"(lo));
    return r;
}

// ---------------------------------------------------------------------------
// Kernel 1: unified init (grid-stride)
// ---------------------------------------------------------------------------
#define IT0 (N_NODES * DIM / 8)
#define IT1 (IT0 + M_PAD * DIM / 8)
#define IT2 (IT1 + N_RELS * DIM / 8)
#define IT3 (IT2 + 256 * DIM / 8)

__global__ void __launch_bounds__(256) init_kernel(
    const float* __restrict__ h,
    const float* __restrict__ rel_emb,
    const float* __restrict__ W_neighbor,
    const float* __restrict__ loop_weight)
{
    for (int i = blockIdx.x * 256 + threadIdx.x; i < IT3; i += gridDim.x * 256) {
        if (i < IT0) {
            ((uint4*)g_S16)[i] = make_uint4(0, 0, 0, 0);
        } else if (i < IT1) {
            int j   = i - IT0;
            int row = j >> 4;
            int sg  = j & 15;
            uint4 o = make_uint4(0, 0, 0, 0);
            if (row < N_NODES) {
                const float4* src = (const float4*)(h + (size_t)row * DIM + sg * 8);
                float4 a = src[0], b = src[1];
                o.x = pack_h2(a.x, a.y); o.y = pack_h2(a.z, a.w);
                o.z = pack_h2(b.x, b.y); o.w = pack_h2(b.z, b.w);
            }
            ((uint4*)g_h16)[j] = o;
        } else if (i < IT2) {
            int j = i - IT1;
            const float4* src = (const float4*)(rel_emb + (size_t)j * 8);
            float4 a = src[0], b = src[1];
            uint4 o;
            o.x = pack_h2(a.x, a.y); o.y = pack_h2(a.z, a.w);
            o.z = pack_h2(b.x, b.y); o.w = pack_h2(b.z, b.w);
            ((uint4*)g_rel16)[j] = o;
        } else {
            int j = i - IT2;                 // < 4096
            int k = j >> 4;
            int sg = j & 15;
            const float* src = (k < 128) ? (W_neighbor + (size_t)k * DIM + sg * 8)
                                         : (loop_weight + (size_t)(k - 128) * DIM + sg * 8);
            float4 a = ((const float4*)src)[0], b = ((const float4*)src)[1];
            uint4 o;
            o.x = pack_h2(a.x, a.y); o.y = pack_h2(a.z, a.w);
            o.z = pack_h2(b.x, b.y); o.w = pack_h2(b.z, b.w);
            ((uint4*)g_B)[j] = o;
        }
    }
}

// ---------------------------------------------------------------------------
// Kernel 2: fp16 edge scatter.  16 lanes per edge; each warp covers 4 edges
// (2 pipelined iterations of 2 edges).
// ---------------------------------------------------------------------------
__device__ __forceinline__ void do_edge(
    const int* __restrict__ edge_src, const int* __restrict__ edge_dst,
    const int* __restrict__ edge_type, int e, int l16)
{
    int s = __ldg(edge_src  + e);
    int d = __ldg(edge_dst  + e);
    int t = __ldg(edge_type + e);
    const uint4 hv = *(const uint4*)(g_h16   + (size_t)s * DIM + l16 * 8);
    const uint4 rv = *(const uint4*)(g_rel16 + (size_t)t * DIM + l16 * 8);
    u32 m0, m1, m2, m3;
    asm("add.rn.f16x2 %0, %1, %2;" : "=r"(m0) : "r"(hv.x), "r"(rv.x));
    asm("add.rn.f16x2 %0, %1, %2;" : "=r"(m1) : "r"(hv.y), "r"(rv.y));
    asm("add.rn.f16x2 %0, %1, %2;" : "=r"(m2) : "r"(hv.z), "r"(rv.z));
    asm("add.rn.f16x2 %0, %1, %2;" : "=r"(m3) : "r"(hv.w), "r"(rv.w));
    u16* outp = g_S16 + (size_t)d * DIM + l16 * 8;
    asm volatile("red.global.add.noftz.v4.f16x2 [%0], {%1, %2, %3, %4};"
                 :: "l"(outp), "r"(m0), "r"(m1), "r"(m2), "r"(m3) : "memory");
}

__global__ void __launch_bounds__(256) scatter_edges_kernel(
    const int* __restrict__ edge_src,
    const int* __restrict__ edge_dst,
    const int* __restrict__ edge_type)
{
    int w    = (int)((blockIdx.x * (unsigned)blockDim.x + threadIdx.x) >> 5);
    int lane = threadIdx.x & 31;
    int l16  = lane & 15;
    int e    = w * 4 + (lane >> 4);       // 4 edges per warp: e, e+2 (per 16-group)

    if (e + 2 < N_EDGES) {
        do_edge(edge_src, edge_dst, edge_type, e, l16);
        do_edge(edge_src, edge_dst, edge_type, e + 2, l16);
    } else if (e < N_EDGES) {
        do_edge(edge_src, edge_dst, edge_type, e, l16);
        if (e + 2 < N_EDGES) do_edge(edge_src, edge_dst, edge_type, e + 2, l16);
    }
}

// ---------------------------------------------------------------------------
// Kernel 3: fused GEMM, fp16, pure cp.async staging (R13 config, unchanged).
//   out = relu( norm .* (S @ Wn) + h @ Wl )
// K chunks 0-1 = S, 2-3 = h; norm applied to accumulators after chunk 1.
// CTA 256 thr / 8 warps, tile 128x128, warp 32x64.  2 CTAs/SM (71.7KB smem).
// ---------------------------------------------------------------------------
#define A_STRIDE 144
#define B_STRIDE 272
#define OFF_A(s) ((s) * 18432)
#define OFF_B(s) (36864 + (s) * 17408)
#define SM_TOTAL 71680

__device__ __forceinline__ void ldsm4(u32* r, u32 addr) {
    asm volatile("ldmatrix.sync.aligned.m8n8.x4.shared.b16 {%0,%1,%2,%3}, [%4];"
                 : "=r"(r[0]), "=r"(r[1]), "=r"(r[2]), "=r"(r[3]) : "r"(addr));
}
__device__ __forceinline__ void ldsm4t(u32* r, u32 addr) {
    asm volatile("ldmatrix.sync.aligned.m8n8.x4.trans.shared.b16 {%0,%1,%2,%3}, [%4];"
                 : "=r"(r[0]), "=r"(r[1]), "=r"(r[2]), "=r"(r[3]) : "r"(addr));
}
__device__ __forceinline__ void mma16816(float* d, const u32* a, u32 b0, u32 b1) {
    asm volatile("mma.sync.aligned.m16n8k16.row.col.f32.f16.f16.f32 "
                 "{%0,%1,%2,%3}, {%4,%5,%6,%7}, {%8,%9}, {%0,%1,%2,%3};"
                 : "+f"(d[0]), "+f"(d[1]), "+f"(d[2]), "+f"(d[3])
                 : "r"(a[0]), "r"(a[1]), "r"(a[2]), "r"(a[3]), "r"(b0), "r"(b1));
}
__device__ __forceinline__ void cp16(u32 dst, const void* src) {
    asm volatile("cp.async.cg.shared.global [%0], [%1], 16;" :: "r"(dst), "l"(src) : "memory");
}
#define CP_COMMIT() asm volatile("cp.async.commit_group;" ::: "memory")

__device__ __forceinline__ void issue_chunk(u32 sbase, int tid, int row0, int c, int s)
{
    const u16* asrc = (c < 2) ? g_S16 : g_h16;
    int koff = (c & 1) * 64;
    u32 ab = sbase + OFF_A(s);
#pragma unroll
    for (int it = 0; it < 4; it++) {
        int i  = tid + it * 256;           // < 1024
        int r  = i >> 3;
        int sg = i & 7;
        cp16(ab + (u32)(r * A_STRIDE + sg * 16),
             (const char*)(asrc + (size_t)(row0 + r) * DIM + koff) + sg * 16);
    }
    u32 bb = sbase + OFF_B(s);
#pragma unroll
    for (int it = 0; it < 4; it++) {
        int i  = tid + it * 256;           // < 1024
        int r  = i >> 4;
        int sg = i & 15;
        cp16(bb + (u32)(r * B_STRIDE + sg * 16),
             (const char*)g_B + (size_t)(c * 64 + r) * 256 + sg * 16);
    }
}

__global__ void __launch_bounds__(256, 2) gemm_fused_kernel(
    const float* __restrict__ norm,
    float* __restrict__ out)
{
    extern __shared__ char smem[];
    u32 sbase;
    asm("{ .reg .u64 t; cvta.to.shared.u64 t, %1; cvt.u32.u64 %0, t; }"
        : "=r"(sbase) : "l"(smem));

    const int tid    = threadIdx.x;
    const int wid    = tid >> 5;
    const int lane   = tid & 31;
    const int warp_m = wid & 3;
    const int warp_n = wid >> 2;
    const int row0   = blockIdx.x * 128;

    float nrm[2][2];
#pragma unroll
    for (int mi = 0; mi < 2; mi++) {
        int r0 = row0 + warp_m * 32 + mi * 16 + (lane >> 2);
        nrm[mi][0] = (r0     < N_NODES) ? __ldg(norm + r0)     : 0.f;
        nrm[mi][1] = (r0 + 8 < N_NODES) ? __ldg(norm + r0 + 8) : 0.f;
    }

    issue_chunk(sbase, tid, row0, 0, 0);
    CP_COMMIT();
    issue_chunk(sbase, tid, row0, 1, 1);
    CP_COMMIT();

    float acc[2][8][4];
#pragma unroll
    for (int mi = 0; mi < 2; mi++)
#pragma unroll
        for (int ni = 0; ni < 8; ni++)
#pragma unroll
            for (int q = 0; q < 4; q++) acc[mi][ni][q] = 0.f;

#pragma unroll
    for (int c = 0; c < 4; c++) {
        const int s = c & 1;
        if (c < 3) asm volatile("cp.async.wait_group 1;" ::: "memory");
        else       asm volatile("cp.async.wait_group 0;" ::: "memory");
        __syncthreads();

        const u32 a_sm = sbase + OFF_A(s);
        const u32 b_sm = sbase + OFF_B(s);
#pragma unroll
        for (int k16 = 0; k16 < 4; k16++) {
            u32 bh[4][4];
#pragma unroll
            for (int ng = 0; ng < 4; ng++) {
                u32 baddr = b_sm
                          + (u32)((k16 * 16 + (lane & 15)) * B_STRIDE)
                          + (u32)((warp_n * 64 + ng * 16 + (lane >> 4) * 8) * 2);
                ldsm4t(bh[ng], baddr);
            }
#pragma unroll
            for (int mi = 0; mi < 2; mi++) {
                u32 aaddr = a_sm
                          + (u32)((warp_m * 32 + mi * 16 + (lane & 15)) * A_STRIDE)
                          + (u32)(k16 * 32 + (lane >> 4) * 16);
                u32 ah[4];
                ldsm4(ah, aaddr);
#pragma unroll
                for (int ni = 0; ni < 8; ni++) {
                    int ng = ni >> 1;
                    int hf = (ni & 1) * 2;
                    mma16816(acc[mi][ni], ah, bh[ng][hf], bh[ng][hf + 1]);
                }
            }
        }

        if (c == 1) {
#pragma unroll
            for (int mi = 0; mi < 2; mi++)
#pragma unroll
                for (int ni = 0; ni < 8; ni++) {
                    acc[mi][ni][0] *= nrm[mi][0];
                    acc[mi][ni][1] *= nrm[mi][0];
                    acc[mi][ni][2] *= nrm[mi][1];
                    acc[mi][ni][3] *= nrm[mi][1];
                }
        }

        if (c < 2) {
            __syncthreads();
            issue_chunk(sbase, tid, row0, c + 2, s);
            CP_COMMIT();
        }
    }

    // epilogue: relu + store (32x64 per warp)
#pragma unroll
    for (int mi = 0; mi < 2; mi++) {
        int r0 = row0 + warp_m * 32 + mi * 16 + (lane >> 2);
#pragma unroll
        for (int ni = 0; ni < 8; ni++) {
            int col = warp_n * 64 + ni * 8 + (lane & 3) * 2;
            if (r0 < N_NODES) {
                float2 v;
                v.x = fmaxf(acc[mi][ni][0], 0.f);
                v.y = fmaxf(acc[mi][ni][1], 0.f);
                *(float2*)(out + (size_t)r0 * DIM + col) = v;
            }
            if (r0 + 8 < N_NODES) {
                float2 v;
                v.x = fmaxf(acc[mi][ni][2], 0.f);
                v.y = fmaxf(acc[mi][ni][3], 0.f);
                *(float2*)(out + (size_t)(r0 + 8) * DIM + col) = v;
            }
        }
    }
}

// ---------------------------------------------------------------------------
// Launcher
// ---------------------------------------------------------------------------
extern "C" void kernel_launch(void* const* d_in, const int* in_sizes, int n_in,
                              void* d_out, int out_size)
{
    (void)in_sizes; (void)n_in; (void)out_size;

    const float* h          = (const float*)d_in[0];
    const float* norm       = (const float*)d_in[1];
    const float* rel_emb    = (const float*)d_in[2];
    const float* W_neighbor = (const float*)d_in[3];
    const float* loop_w     = (const float*)d_in[4];
    const int*   edge_src   = (const int*)d_in[5];
    const int*   edge_dst   = (const int*)d_in[6];
    const int*   edge_type  = (const int*)d_in[7];
    float*       out        = (float*)d_out;

    init_kernel<<<1184, 256>>>(h, rel_emb, W_neighbor, loop_w);
    {
        // 4 edges per warp
        long long warps = (N_EDGES + 3) / 4;
        long long threads = warps * 32;
        scatter_edges_kernel<<<(int)((threads + 255) / 256), 256>>>(edge_src, edge_dst, edge_type);
    }
    {
        static bool attr_set = false;
        if (!attr_set) {
            cudaFuncSetAttribute(gemm_fused_kernel,
                                 cudaFuncAttributeMaxDynamicSharedMemorySize, SM_TOTAL);
            attr_set = true;
        }
        gemm_fused_kernel<<<NTILES, 256, SM_TOTAL>>>(norm, out);
    }
}